// round 15
// baseline (speedup 1.0000x reference)
#include <cuda_runtime.h>
#include <cuda_bf16.h>

#define BATCH 4
#define NPTS  16384
#define MCTR  4096
#define KNB   32
#define R2    0.01f
#define RMARG 0.1005f
#define RM2   (RMARG * RMARG)
#define CH    6
#define NCELL 1000          // 10x10x10 per batch
#define TCELL 4096
#define CAP   128
#define NPTOT (BATCH * NPTS)   // 65536

// Scratch (__device__ globals: allocation-guard-safe, zero-initialized)
__device__ float4 g_pts4 [NPTOT];      // orig order (x,y,z,p2)
__device__ float4 g_spts4[NPTOT];      // cell-sorted (x,y,z,bitcast idx)
__device__ int    g_pk   [NPTOT];      // packed cell | rank<<12
__device__ int    g_cnt  [TCELL];      // re-zeroed each pass (by scatter)
__device__ int    g_off  [TCELL + 1];

// ---------------------------------------------------------------------------
// pack + count: 4 points/thread, float4 stream loads (MLP=3), packed pk
// ---------------------------------------------------------------------------
__global__ __launch_bounds__(256) void pack_count_kernel(const float* __restrict__ pts) {
    int t = blockIdx.x * blockDim.x + threadIdx.x;     // 0..16383
    int b  = t >> 12;                                  // NPTS/4 = 4096 threads/batch
    int n4 = (t & 4095) << 2;
    const float* p = pts + (size_t)b * 3 * NPTS;

    float4 xv = *reinterpret_cast<const float4*>(p + n4);
    float4 yv = *reinterpret_cast<const float4*>(p + NPTS + n4);
    float4 zv = *reinterpret_cast<const float4*>(p + 2 * NPTS + n4);

    float xs[4] = {xv.x, xv.y, xv.z, xv.w};
    float ys[4] = {yv.x, yv.y, yv.z, yv.w};
    float zs[4] = {zv.x, zv.y, zv.z, zv.w};

    int gbase = b * NPTS + n4;
    #pragma unroll
    for (int i = 0; i < 4; i++) {
        float x = xs[i], y = ys[i], z = zs[i];
        float p2 = __fmaf_rn(z, z, __fmaf_rn(y, y, __fmul_rn(x, x)));
        g_pts4[gbase + i] = make_float4(x, y, z, p2);
        int ci = min(9, max(0, (int)(x * 10.0f)));
        int cj = min(9, max(0, (int)(y * 10.0f)));
        int ck = min(9, max(0, (int)(z * 10.0f)));
        int gc = b * NCELL + (ci * 10 + cj) * 10 + ck;
        int rank = atomicAdd(&g_cnt[gc], 1);
        g_pk[gbase + i] = gc | (rank << 12);
    }
}

// ---------------------------------------------------------------------------
// exclusive scan over 4096 counts — warp-shuffle 2-level, single block
// ---------------------------------------------------------------------------
__global__ __launch_bounds__(1024) void scan_kernel() {
    __shared__ int wsum[32];
    int tid  = threadIdx.x;
    int lane = tid & 31, wid = tid >> 5;

    int i0 = tid * 4;
    int v0 = g_cnt[i0], v1 = g_cnt[i0 + 1], v2 = g_cnt[i0 + 2], v3 = g_cnt[i0 + 3];
    int local = v0 + v1 + v2 + v3;

    int inc = local;
    #pragma unroll
    for (int d = 1; d < 32; d <<= 1) {
        int t = __shfl_up_sync(0xffffffffu, inc, d);
        if (lane >= d) inc += t;
    }
    if (lane == 31) wsum[wid] = inc;
    __syncthreads();
    if (wid == 0) {
        int w = wsum[lane];
        int winc = w;
        #pragma unroll
        for (int d = 1; d < 32; d <<= 1) {
            int t = __shfl_up_sync(0xffffffffu, winc, d);
            if (lane >= d) winc += t;
        }
        wsum[lane] = winc - w;
    }
    __syncthreads();

    int excl = wsum[wid] + inc - local;
    g_off[i0]     = excl;
    g_off[i0 + 1] = excl + v0;
    g_off[i0 + 2] = excl + v0 + v1;
    g_off[i0 + 3] = excl + v0 + v1 + v2;
    if (tid == 1023) g_off[TCELL] = excl + local;
}

// ---------------------------------------------------------------------------
// atomic-free scatter, 2 points/thread (independent chains); re-zeroes g_cnt
// ---------------------------------------------------------------------------
__global__ __launch_bounds__(256) void scatter_kernel() {
    int t = blockIdx.x * blockDim.x + threadIdx.x;   // 0..32767
    if (t < TCELL) g_cnt[t] = 0;

    int t0 = t, t1 = t + NPTOT / 2;
    int pk0 = g_pk[t0];
    int pk1 = g_pk[t1];
    float4 p0 = g_pts4[t0];
    float4 p1 = g_pts4[t1];
    int off0 = g_off[pk0 & 4095];
    int off1 = g_off[pk1 & 4095];
    int n0 = t0 & (NPTS - 1), n1 = t1 & (NPTS - 1);
    g_spts4[off0 + (pk0 >> 12)] = make_float4(p0.x, p0.y, p0.z, __int_as_float(n0));
    g_spts4[off1 + (pk1 >> 12)] = make_float4(p1.x, p1.y, p1.z, __int_as_float(n1));
}

// ---------------------------------------------------------------------------
// warp selection primitives (ascending, 32 elements across lanes)
// ---------------------------------------------------------------------------
__device__ __forceinline__ int sort32(int v, int lane) {
    #pragma unroll
    for (int k = 2; k <= 32; k <<= 1) {
        #pragma unroll
        for (int j = k >> 1; j > 0; j >>= 1) {
            int part = __shfl_xor_sync(0xffffffffu, v, j);
            bool up = ((lane & k) == 0);
            bool takeMin = (((lane & j) == 0) == up);
            v = takeMin ? min(v, part) : max(v, part);
        }
    }
    return v;
}

__device__ __forceinline__ int merge_lower32(int a, int b, int lane) {
    int brev = __shfl_sync(0xffffffffu, b, 31 - lane);
    int m = min(a, brev);
    #pragma unroll
    for (int j = 16; j > 0; j >>= 1) {
        int part = __shfl_xor_sync(0xffffffffu, m, j);
        bool takeMin = ((lane & j) == 0);
        m = takeMin ? min(m, part) : max(m, part);
    }
    return m;
}

// ---------------------------------------------------------------------------
// warp-per-center query + fused grouping epilogue (R14, unchanged)
// ---------------------------------------------------------------------------
__global__ __launch_bounds__(256) void query_kernel(const float* __restrict__ centers,
                                                    float* __restrict__ out) {
    __shared__ int   lists[8][CAP];          // 4 KB
    __shared__ float stage[CH][8][33];       // 6.2 KB

    int gw   = (blockIdx.x * blockDim.x + threadIdx.x) >> 5;
    int wslt = threadIdx.x >> 5;
    int lane = threadIdx.x & 31;
    int b = gw / MCTR, m = gw - b * MCTR;

    const float* c = centers + (size_t)b * 3 * MCTR;
    float cx = c[m], cy = c[MCTR + m], cz = c[2 * MCTR + m];
    float c2 = __fmaf_rn(cz, cz, __fmaf_rn(cy, cy, __fmul_rn(cx, cx)));

    int i0 = max(0, (int)((cx - RMARG) * 10.0f)), i1 = min(9, (int)((cx + RMARG) * 10.0f));
    int j0 = max(0, (int)((cy - RMARG) * 10.0f)), j1 = min(9, (int)((cy + RMARG) * 10.0f));
    int k0 = max(0, (int)((cz - RMARG) * 10.0f)), k1 = min(9, (int)((cz + RMARG) * 10.0f));

    int* lst = lists[wslt];
    unsigned below = (1u << lane) - 1u;
    unsigned cnt = 0;

    for (int ci = i0; ci <= i1; ci++) {
        float lox = ci * 0.1f, hix = lox + 0.1f;
        float dxm = fmaxf(fmaxf(lox - cx, cx - hix), 0.0f);
        float dx2 = dxm * dxm;
        for (int cj = j0; cj <= j1; cj++) {
            float loy = cj * 0.1f, hiy = loy + 0.1f;
            float dym = fmaxf(fmaxf(loy - cy, cy - hiy), 0.0f);
            if (__fmaf_rn(dym, dym, dx2) >= RM2) continue;   // column prune

            int cb = b * NCELL + (ci * 10 + cj) * 10;        // z-cells contiguous
            int start = g_off[cb + k0];
            int end   = g_off[cb + k1 + 1];
            for (int pb = start; pb < end; pb += 64) {
                int p0 = pb + lane;
                int p1 = pb + 32 + lane;
                bool h0 = false, h1 = false;
                int iv0 = 0, iv1 = 0;
                if (p0 < end) {
                    float4 q = g_spts4[p0];
                    float p2 = __fmaf_rn(q.z, q.z, __fmaf_rn(q.y, q.y, __fmul_rn(q.x, q.x)));
                    float cp = __fmaf_rn(cz, q.z, __fmaf_rn(cy, q.y, __fmul_rn(cx, q.x)));
                    float d2 = __fsub_rn(__fadd_rn(c2, p2), __fmul_rn(2.0f, cp));
                    h0 = d2 < R2;
                    iv0 = __float_as_int(q.w);
                }
                if (p1 < end) {
                    float4 q = g_spts4[p1];
                    float p2 = __fmaf_rn(q.z, q.z, __fmaf_rn(q.y, q.y, __fmul_rn(q.x, q.x)));
                    float cp = __fmaf_rn(cz, q.z, __fmaf_rn(cy, q.y, __fmul_rn(cx, q.x)));
                    float d2 = __fsub_rn(__fadd_rn(c2, p2), __fmul_rn(2.0f, cp));
                    h1 = d2 < R2;
                    iv1 = __float_as_int(q.w);
                }
                unsigned m0 = __ballot_sync(0xffffffffu, h0);
                unsigned m1 = __ballot_sync(0xffffffffu, h1);

                unsigned s0 = cnt + __popc(m0 & below);
                if (h0 && s0 < CAP) lst[s0] = iv0;
                unsigned cmid = cnt + __popc(m0);
                unsigned s1 = cmid + __popc(m1 & below);
                if (h1 && s1 < CAP) lst[s1] = iv1;
                cnt = cmid + __popc(m1);
            }
        }
    }

    int eff = min((int)cnt, CAP);
    int ng  = (eff <= 32) ? 1 : (eff <= 64) ? 2 : (eff <= 96) ? 3 : 4;
    for (int t = eff + lane; t < ng * 32; t += 32) lst[t] = 0x7fffffff;
    __syncwarp();

    int top;
    {
        int a = sort32(lst[lane], lane);
        if (ng == 1) {
            top = a;
        } else {
            int bb = sort32(lst[32 + lane], lane);
            int m01 = merge_lower32(a, bb, lane);
            if (ng == 2) {
                top = m01;
            } else {
                int cc = sort32(lst[64 + lane], lane);
                if (ng == 3) {
                    top = merge_lower32(m01, cc, lane);
                } else {
                    int dd = sort32(lst[96 + lane], lane);
                    top = merge_lower32(m01, merge_lower32(cc, dd, lane), lane);
                }
            }
        }
    }

    // ----- fused grouping epilogue -----
    int topidx = (lane < eff) ? top : 0;                 // reference zero-pads
    float4 pq = g_pts4[(size_t)b * NPTS + topidx];

    stage[0][wslt][lane] = pq.x;
    stage[1][wslt][lane] = pq.y;
    stage[2][wslt][lane] = pq.z;
    stage[3][wslt][lane] = __fsub_rn(pq.x, cx);
    stage[4][wslt][lane] = __fsub_rn(pq.y, cy);
    stage[5][wslt][lane] = __fsub_rn(pq.z, cz);
    __syncthreads();

    int tid   = threadIdx.x;
    int mbase = (blockIdx.x * 8) & (MCTR - 1);
    float* ob = out + (size_t)b * (CH * KNB) * MCTR + mbase;

    #pragma unroll
    for (int pass = 0; pass < 2; pass++) {
        int r = (tid >> 1) + pass * 128;
        if (r < CH * KNB) {
            int cch = r >> 5, kk = r & 31;
            int mh = (tid & 1) * 4;
            float v0 = stage[cch][mh + 0][kk];
            float v1 = stage[cch][mh + 1][kk];
            float v2 = stage[cch][mh + 2][kk];
            float v3 = stage[cch][mh + 3][kk];
            *reinterpret_cast<float4*>(ob + (size_t)r * MCTR + mh) =
                make_float4(v0, v1, v2, v3);
        }
    }
}

// ---------------------------------------------------------------------------
extern "C" void kernel_launch(void* const* d_in, const int* in_sizes, int n_in,
                              void* d_out, int out_size) {
    const float* pts = (const float*)d_in[0];
    const float* ctr = (const float*)d_in[1];
    if (n_in >= 2 && in_sizes[0] < in_sizes[1]) {
        const float* t = pts; pts = ctr; ctr = t;
    }
    float* out = (float*)d_out;

    pack_count_kernel<<<(NPTOT / 4) / 256, 256>>>(pts);
    scan_kernel<<<1, 1024>>>();
    scatter_kernel<<<(NPTOT / 2) / 256, 256>>>();
    query_kernel<<<(BATCH * MCTR) / 8, 256>>>(ctr, out);
}